// round 9
// baseline (speedup 1.0000x reference)
#include <cuda_runtime.h>

#define NN 512
#define TP 16

typedef unsigned long long ull;

// ---------- f32x2 packed helpers ----------
__device__ __forceinline__ ull pk2(float lo, float hi) {
    ull r; asm("mov.b64 %0, {%1, %2};" : "=l"(r) : "f"(lo), "f"(hi)); return r;
}
__device__ __forceinline__ void upk2(float& lo, float& hi, ull v) {
    asm("mov.b64 {%0, %1}, %2;" : "=f"(lo), "=f"(hi) : "l"(v));
}
__device__ __forceinline__ void ffma2(ull& acc, ull a, ull b) {
    asm("fma.rn.f32x2 %0, %1, %2, %0;" : "+l"(acc) : "l"(a), "l"(b));
}

// ---------------- scratch ----------------
__device__ float g_XW1a[NN * TP * 32];
__device__ float g_XW1b[NN * TP * 32];
__device__ float g_XW2a[NN * TP * 32];
__device__ float g_XW2b[NN * TP * 32];
__device__ float g_Q[NN * 32];
__device__ float g_QB[NN * TP];
__device__ float g_RA[NN * TP];
__device__ float g_L1[NN * NN];    // logits1 -> s1
__device__ float g_L2T[NN * NN];   // logits2^T -> s2^T
__device__ float g_r1[NN * TP];
__device__ float g_c2[NN * TP];
__device__ float g_acc[NN * 32];

// ---------------- k1: XW1a/b, XW2a/b, Q, QB, RA ----------------
__global__ void k1_precompute(const float* __restrict__ x,
                              const float* __restrict__ W1,
                              const float* __restrict__ W2,
                              const float* __restrict__ W3) {
    int n0 = blockIdx.x * 4;
    __shared__ float xs[4][16];
    int tid = threadIdx.x;
    if (tid < 64) xs[tid / 16][tid % 16] = x[(n0 + tid / 16) * 16 + (tid % 16)];
    __syncthreads();

    for (int th = tid; th < 512; th += 256) {
        float a1[4] = {0,0,0,0}, b1[4] = {0,0,0,0};
        float a2[4] = {0,0,0,0}, b2[4] = {0,0,0,0};
        for (int i = 0; i < 16; i++) {
            float w1a = W1[i * 512 + th];
            float w1b = W1[(i + 16) * 512 + th];
            float w2a = W2[i * 512 + th];
            float w2b = W2[(i + 16) * 512 + th];
#pragma unroll
            for (int j = 0; j < 4; j++) {
                float xv = xs[j][i];
                a1[j] += xv * w1a; b1[j] += xv * w1b;
                a2[j] += xv * w2a; b2[j] += xv * w2b;
            }
        }
#pragma unroll
        for (int j = 0; j < 4; j++) {
            g_XW1a[(n0 + j) * 512 + th] = a1[j];
            g_XW1b[(n0 + j) * 512 + th] = b1[j];
            g_XW2a[(n0 + j) * 512 + th] = a2[j];
            g_XW2b[(n0 + j) * 512 + th] = b2[j];
        }
    }
    if (tid < 32) {
#pragma unroll
        for (int j = 0; j < 4; j++) {
            float acc = 0.f;
            for (int i = 0; i < 16; i++) acc += xs[j][i] * W3[i * 32 + tid];
            g_Q[(n0 + j) * 32 + tid] = acc;
        }
    }
    __syncthreads();
    if (tid < 64) {
        int n = n0 + tid / 16, t = tid % 16;
        const float* q  = g_Q + n * 32;
        const float* wa = g_XW1a + n * 512 + t * 32;
        const float* wb = g_XW1b + n * 512 + t * 32;
        float ra = 0.f, qb = 0.f;
#pragma unroll
        for (int h = 0; h < 32; h++) { float qv = q[h]; ra += qv * wa[h]; qb += qv * wb[h]; }
        g_RA[n * 16 + t] = ra;
        g_QB[n * 16 + t] = qb;
    }
}

// ---------------- k2: fused logits + zero accumulators ----------------
__global__ void __launch_bounds__(512) k2_logits(const float* __restrict__ adj) {
    int tid = threadIdx.x;
    int bid = blockIdx.y * 16 + blockIdx.x;
    if (bid < 32)      g_acc[bid * 512 + tid] = 0.f;
    else if (bid < 48) g_r1[(bid - 32) * 512 + tid] = 0.f;
    else if (bid < 64) g_c2[(bid - 48) * 512 + tid] = 0.f;

    int a0 = blockIdx.y * 32, b0 = blockIdx.x * 32;
    int bl = tid >> 4, t = tid & 15;
    int bg = b0 + bl;

    __shared__ ull   Qs[32][16];
    __shared__ float QBs[32][16], RAs[32][16];
    {
        int a = tid >> 4, p = tid & 15;
        float2 v = *((const float2*)(g_Q + (a0 + a) * 32) + p);
        Qs[a][p]  = pk2(v.x, v.y);
        QBs[a][p] = g_QB[(a0 + a) * 16 + p];
        RAs[a][p] = g_RA[(a0 + a) * 16 + p];
    }
    ull wa[16], wb[16];
    {
        const float4* pa = (const float4*)(g_XW1a + (bg * 16 + t) * 32);
        const float4* pb = (const float4*)(g_XW1b + (bg * 16 + t) * 32);
#pragma unroll
        for (int v = 0; v < 8; v++) {
            float4 fa = pa[v], fb = pb[v];
            wa[2 * v] = pk2(fa.x, fa.y); wa[2 * v + 1] = pk2(fa.z, fa.w);
            wb[2 * v] = pk2(fb.x, fb.y); wb[2 * v + 1] = pk2(fb.z, fb.w);
        }
    }
    __syncthreads();

    bool hasT = (t < 15);
    const float* pR = adj + ((long)a0 * 512 + bg) * 15 + t;
    const float* pC = adj + ((long)bg * 512 + a0) * 15 + t;

    float arN = 0.f, acN = 0.f;
    if (hasT) { arN = __ldg(pR); acN = __ldg(pC); }

    for (int al = 0; al < 32; al++) {
        float ar = arN, ac = acN;
        if (hasT && al < 31) {
            arN = __ldg(pR + (al + 1) * 7680);
            acN = __ldg(pC + (al + 1) * 15);
        }
        int ag = a0 + al;
        ull acc1 = 0ull, acc2 = 0ull;
        const ulonglong2* qrow = (const ulonglong2*)Qs[al];
#pragma unroll
        for (int j = 0; j < 8; j++) {
            ulonglong2 q = qrow[j];
            ffma2(acc1, q.x, wa[2 * j]);
            ffma2(acc1, q.y, wa[2 * j + 1]);
            ffma2(acc2, q.x, wb[2 * j]);
            ffma2(acc2, q.y, wb[2 * j + 1]);
        }
        float lo, hi;
        upk2(lo, hi, acc1); float p1 = lo + hi;
        upk2(lo, hi, acc2); float p2 = lo + hi;

        float l1p, l2p;
        if (hasT) {
            l1p = ar * p1 + ac * QBs[al][t];
            l2p = ac * RAs[al][t] + ar * p2;
        } else {
            bool dg = (ag == bg);
            l1p = dg ? (p1 + QBs[al][15]) : 0.f;
            l2p = dg ? (RAs[al][15] + p2) : 0.f;
        }
        float u = l1p + __shfl_xor_sync(0xffffffffu, l1p, 8);
        float v = l2p + __shfl_xor_sync(0xffffffffu, l2p, 8);
        float w = (t & 8) ? v : u;
        w += __shfl_xor_sync(0xffffffffu, w, 4);
        w += __shfl_xor_sync(0xffffffffu, w, 2);
        w += __shfl_xor_sync(0xffffffffu, w, 1);
        if (t == 0) g_L1[ag * 512 + bg]  = w;
        if (t == 8) g_L2T[ag * 512 + bg] = w;
    }
}

// ---------------- k5: row softmax ----------------
__global__ void k5_softmax() {
    int r = blockIdx.x;
    float* row = (r < 512) ? (g_L1 + r * 512) : (g_L2T + (r - 512) * 512);
    int tid = threadIdx.x;
    __shared__ float red[8];
    float v0 = row[tid], v1 = row[tid + 256];
    float m = fmaxf(v0, v1);
#pragma unroll
    for (int o = 16; o; o >>= 1) m = fmaxf(m, __shfl_xor_sync(0xffffffffu, m, o));
    if ((tid & 31) == 0) red[tid >> 5] = m;
    __syncthreads();
    float bm = red[0];
#pragma unroll
    for (int i = 1; i < 8; i++) bm = fmaxf(bm, red[i]);
    float e0 = __expf(v0 - bm), e1 = __expf(v1 - bm);
    float s = e0 + e1;
#pragma unroll
    for (int o = 16; o; o >>= 1) s += __shfl_xor_sync(0xffffffffu, s, o);
    __syncthreads();
    if ((tid & 31) == 0) red[tid >> 5] = s;
    __syncthreads();
    float bs = red[0] + red[1] + red[2] + red[3] + red[4] + red[5] + red[6] + red[7];
    float inv = 1.0f / bs;
    row[tid] = e0 * inv;
    row[tid + 256] = e1 * inv;
}

// ---------------- k6r: r1/c2 via transpose-tiled COALESCED adj reads ----------------
// grid (16 m-tiles, 16 n-tiles), 480 threads: tid = n*15 + t.
// r1[n,t] = sum_m s1[n,m] adj[m,n,t];  c2[n,t] = sum_m s2t[n,m] adj[m,n,t].
// For fixed m, the 480 threads read 480 consecutive floats of adj -> fully coalesced.
__global__ void __launch_bounds__(480) k6r_rc(const float* __restrict__ adj) {
    int m0 = blockIdx.x * 32;
    int n0 = blockIdx.y * 32;
    int tid = threadIdx.x;
    __shared__ float s1s[32][33], s2s[32][33];
    for (int idx = tid; idx < 1024; idx += 480) {
        int n = idx >> 5, ml = idx & 31;
        s1s[n][ml] = g_L1[(n0 + n) * 512 + m0 + ml];
        s2s[n][ml] = g_L2T[(n0 + n) * 512 + m0 + ml];
    }
    __syncthreads();

    // diagonal slot t=15 (handled exactly once per n, by the diagonal block)
    if (m0 == n0 && tid < 32) {
        atomicAdd(&g_r1[(n0 + tid) * 16 + 15], s1s[tid][tid]);
        atomicAdd(&g_c2[(n0 + tid) * 16 + 15], s2s[tid][tid]);
    }

    int n = tid / 15, t = tid - n * 15;   // 0..31, 0..14
    const float* base = adj + ((long)m0 * 512 + n0) * 15 + tid;  // + ml*7680
    float r1p = 0.f, c2p = 0.f;
#pragma unroll 8
    for (int ml = 0; ml < 32; ml++) {
        float v = __ldg(base + ml * 7680);
        r1p += s1s[n][ml] * v;
        c2p += s2s[n][ml] * v;
    }
    atomicAdd(&g_r1[(n0 + n) * 16 + t], r1p);
    atomicAdd(&g_c2[(n0 + n) * 16 + t], c2p);
}

// ---------------- k7: slim split-variant A-build + 4a x 4d GEMM (no r1/c2) ----------------
// grid (32 m-tiles of 16, 16 a-tiles of 32, 2 variants) = 1024 blocks, 256 threads.
struct K7S {
    ull   Asp[64][16];     // packed a-pairs per 64-kk chunk
    ull   Bsp[64][32];     // B duplicated pairs (b,b)
    float ss[32][17];
    union {
        float adjS[32][61];
        float accS[32][33];
    } u;
};

__global__ void __launch_bounds__(256) k7_fused(const float* __restrict__ adj) {
    extern __shared__ char smem_raw[];
    K7S& S = *reinterpret_cast<K7S*>(smem_raw);
    int m0 = blockIdx.x * 16;
    int a0 = blockIdx.y * 32;
    int var = blockIdx.z;
    int tid = threadIdx.x;

    const float* sSrc = var ? g_L2T : g_L1;
    const float* bSrc = var ? g_XW2b : g_XW2a;

#pragma unroll
    for (int j = 0; j < 2; j++) {
        int idx = tid + j * 256;
        int a = idx >> 4, ml = idx & 15;
        S.ss[a][ml] = sSrc[(a0 + a) * 512 + m0 + ml];
    }

    int pos = tid & 63, ksub = tid >> 6;
    int pa = (pos & 7) * 2;
    int d4 = (pos >> 3) * 4;
    ull acc[2][4];
#pragma unroll
    for (int p = 0; p < 2; p++)
#pragma unroll
        for (int j = 0; j < 4; j++) acc[p][j] = 0ull;

    for (int mc = 0; mc < 4; mc++) {
        int mb = m0 + mc * 4;
        int kbase = mb * 16;
        __syncthreads();
        for (int idx = tid; idx < 480; idx += 256) {
            int a = idx / 15, r4 = (idx % 15) * 4;
            float4 v = *(const float4*)(adj + (long)(a0 + a) * 7680 + mb * 15 + r4);
            float* dst = &S.u.adjS[a][r4];
            dst[0] = v.x; dst[1] = v.y; dst[2] = v.z; dst[3] = v.w;
        }
        for (int idx = tid; idx < 512; idx += 256) {
            int kk = idx >> 3, dd = (idx & 7) * 4;
            float4 b = *(const float4*)(bSrc + (kbase + kk) * 32 + dd);
            ulonglong2 w0, w1;
            w0.x = pk2(b.x, b.x); w0.y = pk2(b.y, b.y);
            w1.x = pk2(b.z, b.z); w1.y = pk2(b.w, b.w);
            *(ulonglong2*)&S.Bsp[kk][dd]     = w0;
            *(ulonglong2*)&S.Bsp[kk][dd + 2] = w1;
        }
        __syncthreads();
#pragma unroll
        for (int j = 0; j < 4; j++) {
            int idx = tid + j * 256;
            int ap = idx & 15, kk = idx >> 4;
            int ml = kk >> 4, t = kk & 15;
            float v[2];
#pragma unroll
            for (int l = 0; l < 2; l++) {
                int a = 2 * ap + l;
                float sv = S.ss[a][mc * 4 + ml];
                if (t < 15) {
                    v[l] = sv * S.u.adjS[a][ml * 15 + t];
                } else {
                    v[l] = (mb + ml == a0 + a) ? sv : 0.f;
                }
            }
            S.Asp[kk][ap] = pk2(v[0], v[1]);
        }
        __syncthreads();
        int kk0 = ksub * 16;
        const ull* pA = &S.Asp[kk0][pa];
        const ull* pB = &S.Bsp[kk0][d4];
#pragma unroll
        for (int i = 0; i < 16; i++) {
            ulonglong2 A  = *(const ulonglong2*)(pA + i * 16);
            ulonglong2 B0 = *(const ulonglong2*)(pB + i * 32);
            ulonglong2 B1 = *(const ulonglong2*)(pB + i * 32 + 2);
            ffma2(acc[0][0], A.x, B0.x); ffma2(acc[0][1], A.x, B0.y);
            ffma2(acc[0][2], A.x, B1.x); ffma2(acc[0][3], A.x, B1.y);
            ffma2(acc[1][0], A.y, B0.x); ffma2(acc[1][1], A.y, B0.y);
            ffma2(acc[1][2], A.y, B1.x); ffma2(acc[1][3], A.y, B1.y);
        }
    }

    for (int s = 0; s < 4; s++) {
        __syncthreads();
        if (ksub == s) {
#pragma unroll
            for (int p = 0; p < 2; p++)
#pragma unroll
                for (int j = 0; j < 4; j++) {
                    float lo, hi; upk2(lo, hi, acc[p][j]);
                    int aa = 2 * pa + 2 * p, dd = d4 + j;
                    if (s == 0) { S.u.accS[aa][dd] = lo; S.u.accS[aa + 1][dd] = hi; }
                    else        { S.u.accS[aa][dd] += lo; S.u.accS[aa + 1][dd] += hi; }
                }
        }
    }
    __syncthreads();
    for (int idx = tid; idx < 1024; idx += 256) {
        int aa = idx >> 5, dd = idx & 31;
        atomicAdd(&g_acc[(a0 + aa) * 32 + dd], S.u.accS[aa][dd]);
    }
}

// ---------------- k7b: epilogue ----------------
__global__ void k7b_epilogue(float* __restrict__ out) {
    int idx = blockIdx.x * 256 + threadIdx.x;
    int n = idx >> 5, d = idx & 31;
    float acc = g_acc[idx];
    const float* r1 = g_r1 + n * 16;
    const float* c2 = g_c2 + n * 16;
    const float* wb = g_XW2b + n * 512 + d;
    const float* wa = g_XW2a + n * 512 + d;
#pragma unroll
    for (int t = 0; t < 16; t++) acc += r1[t] * wb[t * 32] + c2[t] * wa[t * 32];
    out[idx] = fmaxf(acc, 0.2f * acc);
}

// ---------------- launch ----------------
extern "C" void kernel_launch(void* const* d_in, const int* in_sizes, int n_in,
                              void* d_out, int out_size) {
    const float* x   = (const float*)d_in[0];
    const float* adj = (const float*)d_in[1];
    const float* W1  = (const float*)d_in[2];
    const float* W2  = (const float*)d_in[3];
    const float* W3  = (const float*)d_in[4];
    float* out = (float*)d_out;
    (void)in_sizes; (void)n_in; (void)out_size;

    cudaFuncSetAttribute(k7_fused, cudaFuncAttributeMaxDynamicSharedMemorySize,
                         (int)sizeof(K7S));

    k1_precompute<<<128, 256>>>(x, W1, W2, W3);
    k2_logits<<<dim3(16, 16), 512>>>(adj);
    k5_softmax<<<1024, 256>>>();
    k6r_rc<<<dim3(16, 16), 480>>>(adj);
    k7_fused<<<dim3(32, 16, 2), 256, sizeof(K7S)>>>(adj);
    k7b_epilogue<<<64, 256>>>(out);
}

// round 10
// speedup vs baseline: 1.0800x; 1.0800x over previous
#include <cuda_runtime.h>

#define NN 512
#define TP 16

typedef unsigned long long ull;

// ---------- f32x2 packed helpers ----------
__device__ __forceinline__ ull pk2(float lo, float hi) {
    ull r; asm("mov.b64 %0, {%1, %2};" : "=l"(r) : "f"(lo), "f"(hi)); return r;
}
__device__ __forceinline__ void upk2(float& lo, float& hi, ull v) {
    asm("mov.b64 {%0, %1}, %2;" : "=f"(lo), "=f"(hi) : "l"(v));
}
__device__ __forceinline__ void ffma2(ull& acc, ull a, ull b) {
    asm("fma.rn.f32x2 %0, %1, %2, %0;" : "+l"(acc) : "l"(a), "l"(b));
}

// ---------------- scratch ----------------
__device__ float g_XW1a[NN * TP * 32];
__device__ float g_XW1b[NN * TP * 32];
__device__ float g_XW2a[NN * TP * 32];
__device__ float g_XW2b[NN * TP * 32];
__device__ float g_Q[NN * 32];
__device__ float g_QB[NN * TP];
__device__ float g_RA[NN * TP];
__device__ float g_L1[NN * NN];     // logits1 -> s1
__device__ float g_L2T[NN * NN];    // logits2^T -> s2^T
__device__ float g_r1[NN * TP];
__device__ float g_c2[NN * TP];
__device__ float g_G1p[8 * NN * 240];   // G1 partials per m-chunk: [c][n][t*16+i], t<15
__device__ float g_G2p[8 * NN * 240];

// ---------------- k1: XW1a/b, XW2a/b, Q, QB, RA ----------------
__global__ void k1_precompute(const float* __restrict__ x,
                              const float* __restrict__ W1,
                              const float* __restrict__ W2,
                              const float* __restrict__ W3) {
    int n0 = blockIdx.x * 4;
    __shared__ float xs[4][16];
    int tid = threadIdx.x;
    if (tid < 64) xs[tid / 16][tid % 16] = x[(n0 + tid / 16) * 16 + (tid % 16)];
    __syncthreads();

    for (int th = tid; th < 512; th += 256) {
        float a1[4] = {0,0,0,0}, b1[4] = {0,0,0,0};
        float a2[4] = {0,0,0,0}, b2[4] = {0,0,0,0};
        for (int i = 0; i < 16; i++) {
            float w1a = W1[i * 512 + th];
            float w1b = W1[(i + 16) * 512 + th];
            float w2a = W2[i * 512 + th];
            float w2b = W2[(i + 16) * 512 + th];
#pragma unroll
            for (int j = 0; j < 4; j++) {
                float xv = xs[j][i];
                a1[j] += xv * w1a; b1[j] += xv * w1b;
                a2[j] += xv * w2a; b2[j] += xv * w2b;
            }
        }
#pragma unroll
        for (int j = 0; j < 4; j++) {
            g_XW1a[(n0 + j) * 512 + th] = a1[j];
            g_XW1b[(n0 + j) * 512 + th] = b1[j];
            g_XW2a[(n0 + j) * 512 + th] = a2[j];
            g_XW2b[(n0 + j) * 512 + th] = b2[j];
        }
    }
    if (tid < 32) {
#pragma unroll
        for (int j = 0; j < 4; j++) {
            float acc = 0.f;
            for (int i = 0; i < 16; i++) acc += xs[j][i] * W3[i * 32 + tid];
            g_Q[(n0 + j) * 32 + tid] = acc;
        }
    }
    __syncthreads();
    if (tid < 64) {
        int n = n0 + tid / 16, t = tid % 16;
        const float* q  = g_Q + n * 32;
        const float* wa = g_XW1a + n * 512 + t * 32;
        const float* wb = g_XW1b + n * 512 + t * 32;
        float ra = 0.f, qb = 0.f;
#pragma unroll
        for (int h = 0; h < 32; h++) { float qv = q[h]; ra += qv * wa[h]; qb += qv * wb[h]; }
        g_RA[n * 16 + t] = ra;
        g_QB[n * 16 + t] = qb;
    }
}

// ---------------- k2: fused logits + zero r1/c2 ----------------
__global__ void __launch_bounds__(512) k2_logits(const float* __restrict__ adj) {
    int tid = threadIdx.x;
    int bid = blockIdx.y * 16 + blockIdx.x;
    if (bid < 16)      g_r1[bid * 512 + tid] = 0.f;
    else if (bid < 32) g_c2[(bid - 16) * 512 + tid] = 0.f;

    int a0 = blockIdx.y * 32, b0 = blockIdx.x * 32;
    int bl = tid >> 4, t = tid & 15;
    int bg = b0 + bl;

    __shared__ ull   Qs[32][16];
    __shared__ float QBs[32][16], RAs[32][16];
    {
        int a = tid >> 4, p = tid & 15;
        float2 v = *((const float2*)(g_Q + (a0 + a) * 32) + p);
        Qs[a][p]  = pk2(v.x, v.y);
        QBs[a][p] = g_QB[(a0 + a) * 16 + p];
        RAs[a][p] = g_RA[(a0 + a) * 16 + p];
    }
    ull wa[16], wb[16];
    {
        const float4* pa = (const float4*)(g_XW1a + (bg * 16 + t) * 32);
        const float4* pb = (const float4*)(g_XW1b + (bg * 16 + t) * 32);
#pragma unroll
        for (int v = 0; v < 8; v++) {
            float4 fa = pa[v], fb = pb[v];
            wa[2 * v] = pk2(fa.x, fa.y); wa[2 * v + 1] = pk2(fa.z, fa.w);
            wb[2 * v] = pk2(fb.x, fb.y); wb[2 * v + 1] = pk2(fb.z, fb.w);
        }
    }
    __syncthreads();

    bool hasT = (t < 15);
    const float* pR = adj + ((long)a0 * 512 + bg) * 15 + t;
    const float* pC = adj + ((long)bg * 512 + a0) * 15 + t;

    float arN = 0.f, acN = 0.f;
    if (hasT) { arN = __ldg(pR); acN = __ldg(pC); }

    for (int al = 0; al < 32; al++) {
        float ar = arN, ac = acN;
        if (hasT && al < 31) {
            arN = __ldg(pR + (al + 1) * 7680);
            acN = __ldg(pC + (al + 1) * 15);
        }
        int ag = a0 + al;
        ull acc1 = 0ull, acc2 = 0ull;
        const ulonglong2* qrow = (const ulonglong2*)Qs[al];
#pragma unroll
        for (int j = 0; j < 8; j++) {
            ulonglong2 q = qrow[j];
            ffma2(acc1, q.x, wa[2 * j]);
            ffma2(acc1, q.y, wa[2 * j + 1]);
            ffma2(acc2, q.x, wb[2 * j]);
            ffma2(acc2, q.y, wb[2 * j + 1]);
        }
        float lo, hi;
        upk2(lo, hi, acc1); float p1 = lo + hi;
        upk2(lo, hi, acc2); float p2 = lo + hi;

        float l1p, l2p;
        if (hasT) {
            l1p = ar * p1 + ac * QBs[al][t];
            l2p = ac * RAs[al][t] + ar * p2;
        } else {
            bool dg = (ag == bg);
            l1p = dg ? (p1 + QBs[al][15]) : 0.f;
            l2p = dg ? (RAs[al][15] + p2) : 0.f;
        }
        float u = l1p + __shfl_xor_sync(0xffffffffu, l1p, 8);
        float v = l2p + __shfl_xor_sync(0xffffffffu, l2p, 8);
        float w = (t & 8) ? v : u;
        w += __shfl_xor_sync(0xffffffffu, w, 4);
        w += __shfl_xor_sync(0xffffffffu, w, 2);
        w += __shfl_xor_sync(0xffffffffu, w, 1);
        if (t == 0) g_L1[ag * 512 + bg]  = w;
        if (t == 8) g_L2T[ag * 512 + bg] = w;
    }
}

// ---------------- k5: row softmax ----------------
__global__ void k5_softmax() {
    int r = blockIdx.x;
    float* row = (r < 512) ? (g_L1 + r * 512) : (g_L2T + (r - 512) * 512);
    int tid = threadIdx.x;
    __shared__ float red[8];
    float v0 = row[tid], v1 = row[tid + 256];
    float m = fmaxf(v0, v1);
#pragma unroll
    for (int o = 16; o; o >>= 1) m = fmaxf(m, __shfl_xor_sync(0xffffffffu, m, o));
    if ((tid & 31) == 0) red[tid >> 5] = m;
    __syncthreads();
    float bm = red[0];
#pragma unroll
    for (int i = 1; i < 8; i++) bm = fmaxf(bm, red[i]);
    float e0 = __expf(v0 - bm), e1 = __expf(v1 - bm);
    float s = e0 + e1;
#pragma unroll
    for (int o = 16; o; o >>= 1) s += __shfl_xor_sync(0xffffffffu, s, o);
    __syncthreads();
    if ((tid & 31) == 0) red[tid >> 5] = s;
    __syncthreads();
    float bs = red[0] + red[1] + red[2] + red[3] + red[4] + red[5] + red[6] + red[7];
    float inv = 1.0f / bs;
    row[tid] = e0 * inv;
    row[tid + 256] = e1 * inv;
}

// ---------------- k6r: r1/c2 via transpose-tiled coalesced adj reads ----------------
// grid (32 m-tiles of 16, 16 n-tiles), 480 threads: tid = n*15 + t.
__global__ void __launch_bounds__(480) k6r_rc(const float* __restrict__ adj) {
    int m0 = blockIdx.x * 16;
    int n0 = blockIdx.y * 32;
    int tid = threadIdx.x;
    __shared__ float s1s[32][17], s2s[32][17];
    for (int idx = tid; idx < 512; idx += 480) {
        int n = idx >> 4, ml = idx & 15;
        s1s[n][ml] = g_L1[(n0 + n) * 512 + m0 + ml];
        s2s[n][ml] = g_L2T[(n0 + n) * 512 + m0 + ml];
    }
    __syncthreads();

    // diagonal slot t=15: diag element (g,g) lies in this block iff g-n0 = (m0-n0)+ml
    int dn = m0 - n0;
    if ((dn == 0 || dn == 16) && tid < 16) {
        int n = dn + tid;
        atomicAdd(&g_r1[(n0 + n) * 16 + 15], s1s[n][tid]);
        atomicAdd(&g_c2[(n0 + n) * 16 + 15], s2s[n][tid]);
    }

    int n = tid / 15, t = tid - n * 15;
    const float* base = adj + ((long)m0 * 512 + n0) * 15 + tid;
    float r1p = 0.f, c2p = 0.f;
#pragma unroll
    for (int ml = 0; ml < 16; ml++) {
        float v = __ldg(base + ml * 7680);
        r1p += s1s[n][ml] * v;
        c2p += s2s[n][ml] * v;
    }
    atomicAdd(&g_r1[(n0 + n) * 16 + t], r1p);
    atomicAdd(&g_c2[(n0 + n) * 16 + t], c2p);
}

// ---------------- kG: factored contraction G[n,t,i] = sum_m (s*adj)[n,m,t] x[m,i] ----------------
// grid (8 m-chunks of 64, 16 n-tiles), 480 threads = (n 32, t 15). No reductions across threads.
__global__ void __launch_bounds__(480) kG(const float* __restrict__ adj,
                                          const float* __restrict__ x) {
    int m0 = blockIdx.x * 64;
    int n0 = blockIdx.y * 32;
    int tid = threadIdx.x;
    __shared__ float s1s[32][64], s2s[32][64];
    __shared__ ull xp[64][8];

    for (int idx = tid; idx < 2048; idx += 480) {
        int n = idx >> 6, ml = idx & 63;
        s1s[n][ml] = g_L1[(n0 + n) * 512 + m0 + ml];
        s2s[n][ml] = g_L2T[(n0 + n) * 512 + m0 + ml];
    }
    for (int idx = tid; idx < 512; idx += 480) {
        int ml = idx >> 3, ip = idx & 7;
        float2 v = *(const float2*)(x + (m0 + ml) * 16 + ip * 2);
        xp[ml][ip] = pk2(v.x, v.y);
    }
    __syncthreads();

    int n = tid / 15, t = tid - n * 15;   // n 0..31, t 0..14
    ull G1[8], G2[8];
#pragma unroll
    for (int ip = 0; ip < 8; ip++) { G1[ip] = 0ull; G2[ip] = 0ull; }

    const float* ap = adj + (long)(n0 + n) * 7680 + (long)m0 * 15 + t;
#pragma unroll 8
    for (int ml = 0; ml < 64; ml++) {
        float av = __ldg(ap + ml * 15);
        float p1 = s1s[n][ml] * av;
        float p2 = s2s[n][ml] * av;
        ull p1p = pk2(p1, p1), p2p = pk2(p2, p2);
#pragma unroll
        for (int ip = 0; ip < 8; ip++) {
            ull xv = xp[ml][ip];
            ffma2(G1[ip], p1p, xv);
            ffma2(G2[ip], p2p, xv);
        }
    }
    // store: [chunk][n][t*16+i], 16B-aligned
    long base = ((long)blockIdx.x * 512 + n0 + n) * 240 + t * 16;
    float* d1 = g_G1p + base;
    float* d2 = g_G2p + base;
#pragma unroll
    for (int q = 0; q < 4; q++) {
        ulonglong2 v1; v1.x = G1[2 * q]; v1.y = G1[2 * q + 1];
        ulonglong2 v2; v2.x = G2[2 * q]; v2.y = G2[2 * q + 1];
        *(ulonglong2*)(d1 + q * 4) = v1;
        *(ulonglong2*)(d2 + q * 4) = v2;
    }
}

// ---------------- kEpi: reduce G partials + tiny GEMM + r1/c2 tail + lrelu ----------------
// grid 32 (n-tiles of 16), 512 threads = (n 16, d 32).
struct EpiS {
    float Gs1[16][240];
    float Gs2[16][240];
    float W2sa[240][32];
    float W2sb[240][32];
    float r1s[16][16], c2s[16][16];
};

__global__ void __launch_bounds__(512) kEpi(float* __restrict__ out,
                                            const float* __restrict__ W2) {
    extern __shared__ char smem_raw[];
    EpiS& S = *reinterpret_cast<EpiS*>(smem_raw);
    int n0 = blockIdx.x * 16;
    int tid = threadIdx.x;

    // stage W2 (t<15 rows), both halves
    for (int idx = tid; idx < 7680; idx += 512) {
        int ti = idx >> 5, d = idx & 31;
        int i = ti & 15, t = ti >> 4;
        S.W2sa[ti][d] = W2[i * 512 + t * 32 + d];
        S.W2sb[ti][d] = W2[(i + 16) * 512 + t * 32 + d];
    }
    // reduce G chunk-partials into smem
    for (int idx = tid; idx < 3840; idx += 512) {
        int n = idx / 240, ti = idx - n * 240;
        long off = (long)(n0 + n) * 240 + ti;
        float a1 = 0.f, a2 = 0.f;
#pragma unroll
        for (int c = 0; c < 8; c++) {
            a1 += g_G1p[(long)c * 512 * 240 + off];
            a2 += g_G2p[(long)c * 512 * 240 + off];
        }
        S.Gs1[n][ti] = a1;
        S.Gs2[n][ti] = a2;
    }
    if (tid < 256) {
        int n = tid >> 4, t = tid & 15;
        S.r1s[n][t] = g_r1[(n0 + n) * 16 + t];
        S.c2s[n][t] = g_c2[(n0 + n) * 16 + t];
    }
    __syncthreads();

    int n = tid >> 5, d = tid & 31;
    float acc = 0.f;
#pragma unroll 16
    for (int ti = 0; ti < 240; ti++)
        acc += S.Gs1[n][ti] * S.W2sa[ti][d] + S.Gs2[n][ti] * S.W2sb[ti][d];

    int ng = n0 + n;
    const float* wa = g_XW2a + ng * 512 + d;
    const float* wb = g_XW2b + ng * 512 + d;
#pragma unroll
    for (int t = 0; t < 16; t++)
        acc += S.r1s[n][t] * wb[t * 32] + S.c2s[n][t] * wa[t * 32];
    // t=15 diag contributions that used to live in the GEMM's 16th slot
    acc += S.r1s[n][15] * wa[15 * 32] + S.c2s[n][15] * wb[15 * 32];

    out[ng * 32 + d] = fmaxf(acc, 0.2f * acc);
}

// ---------------- launch ----------------
extern "C" void kernel_launch(void* const* d_in, const int* in_sizes, int n_in,
                              void* d_out, int out_size) {
    const float* x   = (const float*)d_in[0];
    const float* adj = (const float*)d_in[1];
    const float* W1  = (const float*)d_in[2];
    const float* W2  = (const float*)d_in[3];
    const float* W3  = (const float*)d_in[4];
    float* out = (float*)d_out;
    (void)in_sizes; (void)n_in; (void)out_size;

    cudaFuncSetAttribute(kEpi, cudaFuncAttributeMaxDynamicSharedMemorySize,
                         (int)sizeof(EpiS));

    k1_precompute<<<128, 256>>>(x, W1, W2, W3);
    k2_logits<<<dim3(16, 16), 512>>>(adj);
    k5_softmax<<<1024, 256>>>();
    k6r_rc<<<dim3(32, 16), 480>>>(adj);
    kG<<<dim3(8, 16), 480>>>(adj, x);
    kEpi<<<32, 512, sizeof(EpiS)>>>(out, W2);
}